// round 9
// baseline (speedup 1.0000x reference)
#include <cuda_runtime.h>
#include <cuda_bf16.h>

// Problem constants
#define D        256
#define DD       65536
#define BATCH    4096
#define T        100
#define DT_STEP  0.05f
#define NPOW     10          // B-powers kept (k=1..10); tail ~4e-6

typedef unsigned int u32;
typedef signed char  s8;

// ---------------------------------------------------------------------------
// Device scratch (static globals; no allocation anywhere)
// ---------------------------------------------------------------------------
__device__ float g_W[11ull * DD];          // B^k, k=1..10 (slot 0 unused)
__device__ float g_Mf[(size_t)T * DD];     // fp32 M[t] = expm(t*dt*A)
__device__ s8    g_Mqh[(size_t)T * DD];    // int8 hi quant of M
__device__ s8    g_Mql[(size_t)T * DD];    // int8 lo quant of M
__device__ s8    g_Xqh[(size_t)BATCH * D];
__device__ s8    g_Xql[(size_t)BATCH * D];
__device__ int   g_amBits[T];              // per-t amax(M[t]) as float bits
__device__ int   g_axBits;                 // amax(X) as float bits

// ---------------------------------------------------------------------------
// PTX helpers (baseline ISA only)
// ---------------------------------------------------------------------------
__device__ __forceinline__ u32 smem_u32(const void* p) {
    u32 a;
    asm("{ .reg .u64 t; cvta.to.shared.u64 t, %1; cvt.u32.u64 %0, t; }" : "=r"(a) : "l"(p));
    return a;
}
__device__ __forceinline__ void cpa16(u32 dst, const void* src) {
    asm volatile("cp.async.cg.shared.global [%0], [%1], 16;" :: "r"(dst), "l"(src) : "memory");
}
__device__ __forceinline__ void cpa_commit() { asm volatile("cp.async.commit_group;" ::: "memory"); }
template <int N>
__device__ __forceinline__ void cpa_wait() {
    asm volatile("cp.async.wait_group %0;" :: "n"(N) : "memory");
}
__device__ __forceinline__ void ldm4(u32* r, u32 a) {
    asm volatile("ldmatrix.sync.aligned.m8n8.x4.shared.b16 {%0,%1,%2,%3}, [%4];"
                 : "=r"(r[0]), "=r"(r[1]), "=r"(r[2]), "=r"(r[3]) : "r"(a));
}
// int8 MMA: m16n8k32, s32 accumulate
__device__ __forceinline__ void imma(int* c, const u32* a, u32 b0, u32 b1) {
    asm volatile("mma.sync.aligned.m16n8k32.row.col.s32.s8.s8.s32 "
                 "{%0,%1,%2,%3}, {%4,%5,%6,%7}, {%8,%9}, {%0,%1,%2,%3};"
                 : "+r"(c[0]), "+r"(c[1]), "+r"(c[2]), "+r"(c[3])
                 : "r"(a[0]), "r"(a[1]), "r"(a[2]), "r"(a[3]), "r"(b0), "r"(b1));
}

#define SWZ(o) ((o) ^ (((o) >> 3) & 0x70))

// two-level int8 quantization: x ~= sh*qh + (sh/128)*ql
__device__ __forceinline__ void quant2(float x, float sh, float ish, float isl,
                                       s8& qh, s8& ql) {
    float h = rintf(x * ish);
    h = fminf(127.0f, fmaxf(-127.0f, h));
    float r = fmaf(-h, sh, x);
    float l = rintf(r * isl);
    l = fminf(127.0f, fmaxf(-127.0f, l));
    qh = (s8)(int)h;
    ql = (s8)(int)l;
}

// ---------------------------------------------------------------------------
// initB: g_W[1] = B = A + I ; zero the amax accumulators
// ---------------------------------------------------------------------------
__global__ void initB_kernel(const float* __restrict__ A) {
    int i = blockIdx.x * blockDim.x + threadIdx.x;   // 0..DD-1
    int r = i >> 8, c = i & 255;
    g_W[DD + i] = A[i] + ((r == c) ? 1.0f : 0.0f);
    if (i < T) g_amBits[i] = 0;
    if (i == 0) g_axBits = 0;
}

// ---------------------------------------------------------------------------
// Batched small 256x256x256 fp32 matmul: C[z] = X @ Y[z]  (proven R5-R7)
// ---------------------------------------------------------------------------
__global__ void __launch_bounds__(256)
mm_batch_kernel(const float* __restrict__ X,
                const float* __restrict__ Y0,
                float* __restrict__ C0)
{
    const float* __restrict__ Y = Y0 + (size_t)blockIdx.z * DD;
    float* __restrict__ C = C0 + (size_t)blockIdx.z * DD;
    const int rowBase = blockIdx.y * 32;
    const int colBase = blockIdx.x * 32;

    __shared__ float Xs[32][34];
    __shared__ float Ys[32][32];

    const int tid = threadIdx.x;
    const int lrow = tid >> 3;
    const int lq   = (tid & 7) * 4;
    const int tx = tid & 15;
    const int ty = tid >> 4;

    const float* xPtr = X + (size_t)(rowBase + lrow) * D + lq;
    const float* yPtr = Y + (size_t)lrow * D + colBase + lq;

    float4 xv = *(const float4*)xPtr;
    float4 yv = *(const float4*)yPtr;

    float a00 = 0.f, a01 = 0.f, a10 = 0.f, a11 = 0.f;

    for (int d0 = 0; d0 < D; d0 += 32) {
        __syncthreads();
        Xs[lq + 0][lrow] = xv.x; Xs[lq + 1][lrow] = xv.y;
        Xs[lq + 2][lrow] = xv.z; Xs[lq + 3][lrow] = xv.w;
        *(float4*)&Ys[lrow][lq] = yv;
        __syncthreads();

        if (d0 + 32 < D) {
            xv = *(const float4*)(xPtr + d0 + 32);
            yv = *(const float4*)(yPtr + (size_t)(d0 + 32) * D);
        }

#pragma unroll
        for (int kk = 0; kk < 32; ++kk) {
            float2 a = *(const float2*)&Xs[kk][ty * 2];
            float2 b = *(const float2*)&Ys[kk][tx * 2];
            a00 += a.x * b.x; a01 += a.x * b.y;
            a10 += a.y * b.x; a11 += a.y * b.y;
        }
    }

    int gr = rowBase + ty * 2;
    int gc = colBase + tx * 2;
    float2 v0; v0.x = a00; v0.y = a01;
    float2 v1; v1.x = a10; v1.y = a11;
    *(float2*)&C[(size_t)gr * D + gc] = v0;
    *(float2*)&C[(size_t)(gr + 1) * D + gc] = v1;
}

// ---------------------------------------------------------------------------
// gen_m: M[t][i] = e^{-t*dt} * sum_{k=0..NPOW} (t*dt)^k/k! * B^k[i] (fp32),
// plus per-t amax reduction. One CTA owns a 512-elem slice across all t.
// ---------------------------------------------------------------------------
__global__ void __launch_bounds__(256)
gen_m_kernel()
{
    __shared__ float sm[NPOW][512];
    const int base = blockIdx.x * 512;
    const int tid = threadIdx.x;
    const int lane = tid & 31;

    for (int v = tid; v < NPOW * 512; v += 256) {
        int k = v >> 9, j = v & 511;
        sm[k][j] = g_W[(size_t)(k + 1) * DD + base + j];
    }
    __syncthreads();

    const int i0 = base + tid;
    const int i1 = base + tid + 256;
    const float id0 = ((i0 >> 8) == (i0 & 255)) ? 1.0f : 0.0f;
    const float id1 = ((i1 >> 8) == (i1 & 255)) ? 1.0f : 0.0f;

    for (int t = 0; t < T; ++t) {
        float s = DT_STEP * (float)t;
        float c = expf(-s);
        float a0 = c * id0, a1 = c * id1;
        float ck = c;
#pragma unroll
        for (int k = 1; k <= NPOW; ++k) {
            ck *= s / (float)k;
            a0 += ck * sm[k - 1][tid];
            a1 += ck * sm[k - 1][tid + 256];
        }
        g_Mf[(size_t)t * DD + i0] = a0;
        g_Mf[(size_t)t * DD + i1] = a1;

        float mx = fmaxf(fabsf(a0), fabsf(a1));
#pragma unroll
        for (int o = 16; o; o >>= 1)
            mx = fmaxf(mx, __shfl_xor_sync(0xFFFFFFFFu, mx, o));
        if (lane == 0)
            atomicMax(&g_amBits[t], __float_as_int(mx));   // positives: int-monotonic
    }
}

// ---------------------------------------------------------------------------
// quant_m: fp32 M -> int8 hi/lo with per-t scale. 4 elems/thread, char4 IO.
// ---------------------------------------------------------------------------
__global__ void quant_m_kernel() {
    size_t i = ((size_t)blockIdx.x * 256 + threadIdx.x) * 4;
    int t = (int)(i >> 16);
    float am = __int_as_float(g_amBits[t]);
    float sh  = am * (1.0f / 127.0f);
    float ish = 127.0f / am;
    float isl = ish * 128.0f;
    float4 v = *(const float4*)(g_Mf + i);
    char4 h, l;
    quant2(v.x, sh, ish, isl, h.x, l.x);
    quant2(v.y, sh, ish, isl, h.y, l.y);
    quant2(v.z, sh, ish, isl, h.z, l.z);
    quant2(v.w, sh, ish, isl, h.w, l.w);
    *(char4*)(g_Mqh + i) = h;
    *(char4*)(g_Mql + i) = l;
}

// ---------------------------------------------------------------------------
// amax_x / quant_x
// ---------------------------------------------------------------------------
__global__ void amax_x_kernel(const float* __restrict__ X0) {
    size_t i = ((size_t)blockIdx.x * 256 + threadIdx.x) * 4;
    float4 v = *(const float4*)(X0 + i);
    float mx = fmaxf(fmaxf(fabsf(v.x), fabsf(v.y)), fmaxf(fabsf(v.z), fabsf(v.w)));
#pragma unroll
    for (int o = 16; o; o >>= 1)
        mx = fmaxf(mx, __shfl_xor_sync(0xFFFFFFFFu, mx, o));
    if ((threadIdx.x & 31) == 0)
        atomicMax(&g_axBits, __float_as_int(mx));
}

__global__ void quant_x_kernel(const float* __restrict__ X0) {
    size_t i = ((size_t)blockIdx.x * 256 + threadIdx.x) * 4;
    float ax = __int_as_float(g_axBits);
    float sh  = ax * (1.0f / 127.0f);
    float ish = 127.0f / ax;
    float isl = ish * 128.0f;
    float4 v = *(const float4*)(X0 + i);
    char4 h, l;
    quant2(v.x, sh, ish, isl, h.x, l.x);
    quant2(v.y, sh, ish, isl, h.y, l.y);
    quant2(v.z, sh, ish, isl, h.z, l.z);
    quant2(v.w, sh, ish, isl, h.w, l.w);
    *(char4*)(g_Xqh + i) = h;
    *(char4*)(g_Xql + i) = l;
}

// ---------------------------------------------------------------------------
// traj_imma: out[b,t,k] = sum_d X0[b,d]*M[t,k,d] via int8 mma.sync split-2.
// CTA tile: 128 (batch) x 128 (k-cols) x K=256. 8 warps, warp tile 64x32.
// Two K-chunks of 128 (128B int8 swizzled rows), both prefetched via cp.async.
// Two s32 accumulator sets: main (hi*hi) and cross (hi*lo + lo*hi, shared
// scale because s_lo = s_hi/128 on both operands).
// grid (32, 2, 100), 256 threads, 1 CTA/SM (regs).
// ---------------------------------------------------------------------------
#define TB_XH 0
#define TB_XL 16384
#define TB_MH 32768
#define TB_ML 49152
#define BUFSZ 65536
#define SMEM_TRAJ (2 * BUFSZ)   // 128 KB dynamic

__global__ void __launch_bounds__(256, 1)
traj_imma_kernel(float* __restrict__ out)
{
    extern __shared__ char dsm[];
    const u32 sb = smem_u32(dsm);
    const int tid = threadIdx.x;
    const int lane = tid & 31;
    const int wid = tid >> 5;
    const int t = blockIdx.z;
    const int bBase = blockIdx.x * 128;
    const int nBase = blockIdx.y * 128;

    const s8* __restrict__ xh = g_Xqh + (size_t)bBase * D;
    const s8* __restrict__ xl = g_Xql + (size_t)bBase * D;
    const s8* __restrict__ mh = g_Mqh + (size_t)t * DD + (size_t)nBase * D;
    const s8* __restrict__ ml = g_Mql + (size_t)t * DD + (size_t)nBase * D;

    // warp tiling: wm in {0,64}, wn in {0,32,64,96}
    const int wm = (wid & 1) * 64;
    const int wn = (wid >> 1) * 32;
    // ldmatrix lane addressing (byte-identical to the bf16-k16 pattern):
    const int aRow  = wm + (lane & 15);
    const u32 aColB = (u32)((lane >> 4) * 16);          // k-byte half of 32B block
    const int bRow  = wn + ((lane >> 4) << 3) + (lane & 7);
    const u32 bColB = (u32)(((lane >> 3) & 1) * 16);

    int accM[4][4][4], accC[4][4][4];
#pragma unroll
    for (int mi = 0; mi < 4; ++mi)
#pragma unroll
        for (int nf = 0; nf < 4; ++nf)
#pragma unroll
            for (int r = 0; r < 4; ++r) { accM[mi][nf][r] = 0; accC[mi][nf][r] = 0; }

    // ---- loader: 4 tiles x 1024 x 16B per chunk, swizzled 128B rows ----
    auto load_chunk = [&](int buf, int cd) {
        u32 sbuf = sb + (u32)buf * BUFSZ;
#pragma unroll
        for (int it = 0; it < 4; ++it) {
            int v = tid + it * 256;
            int r = v >> 3, j = v & 7;
            u32 off = SWZ((u32)(r * 128 + j * 16));
            size_t g = (size_t)r * D + cd + j * 16;
            cpa16(sbuf + TB_XH + off, xh + g);
            cpa16(sbuf + TB_XL + off, xl + g);
            cpa16(sbuf + TB_MH + off, mh + g);
            cpa16(sbuf + TB_ML + off, ml + g);
        }
        cpa_commit();
    };

    auto compute = [&](int buf) {
        const u32 sbuf = sb + (u32)buf * BUFSZ;
#pragma unroll
        for (int k32 = 0; k32 < 4; ++k32) {
            const u32 kb = (u32)(k32 * 32);
            // B fragments: one ldm4 covers n0-15 (frags {r0,r1},{r2,r3})
            u32 bh[8], bl[8];
            u32 o0 = SWZ((u32)(bRow * 128) + kb + bColB);
            u32 o1 = SWZ((u32)((bRow + 16) * 128) + kb + bColB);
            ldm4(bh,     sbuf + TB_MH + o0);
            ldm4(bh + 4, sbuf + TB_MH + o1);
            ldm4(bl,     sbuf + TB_ML + o0);
            ldm4(bl + 4, sbuf + TB_ML + o1);

            u32 af[4][4];
#pragma unroll
            for (int mi = 0; mi < 4; ++mi) {
                u32 oa = SWZ((u32)((aRow + mi * 16) * 128) + kb + aColB);
                ldm4(af[mi], sbuf + TB_XH + oa);
            }
            // main += Ah*Bh ; cross += Ah*Bl
#pragma unroll
            for (int mi = 0; mi < 4; ++mi)
#pragma unroll
                for (int nf = 0; nf < 4; ++nf) {
                    imma(accM[mi][nf], af[mi], bh[nf * 2], bh[nf * 2 + 1]);
                    imma(accC[mi][nf], af[mi], bl[nf * 2], bl[nf * 2 + 1]);
                }
            // A lo fragments (overwrite) ; cross += Al*Bh
#pragma unroll
            for (int mi = 0; mi < 4; ++mi) {
                u32 oa = SWZ((u32)((aRow + mi * 16) * 128) + kb + aColB);
                ldm4(af[mi], sbuf + TB_XL + oa);
            }
#pragma unroll
            for (int mi = 0; mi < 4; ++mi)
#pragma unroll
                for (int nf = 0; nf < 4; ++nf)
                    imma(accC[mi][nf], af[mi], bh[nf * 2], bh[nf * 2 + 1]);
        }
    };

    load_chunk(0, 0);
    load_chunk(1, 128);

    cpa_wait<1>();
    __syncthreads();
    compute(0);

    cpa_wait<0>();
    __syncthreads();
    compute(1);

    // ---- epilogue: dequantize, out[b, t, k] ----
    const float ax = __int_as_float(g_axBits);
    const float am = __int_as_float(g_amBits[t]);
    const float shh = ax * am * (1.0f / 16129.0f);   // (ax/127)*(am/127)
    const int gr = lane >> 2;
    const int gc = (lane & 3) * 2;
#pragma unroll
    for (int mi = 0; mi < 4; ++mi) {
#pragma unroll
        for (int nf = 0; nf < 4; ++nf) {
            int r0 = bBase + wm + mi * 16 + gr;
            int c0 = nBase + wn + nf * 8 + gc;
            float2 v0, v1;
            v0.x = shh * ((float)accM[mi][nf][0] + 0.0078125f * (float)accC[mi][nf][0]);
            v0.y = shh * ((float)accM[mi][nf][1] + 0.0078125f * (float)accC[mi][nf][1]);
            v1.x = shh * ((float)accM[mi][nf][2] + 0.0078125f * (float)accC[mi][nf][2]);
            v1.y = shh * ((float)accM[mi][nf][3] + 0.0078125f * (float)accC[mi][nf][3]);
            *(float2*)(out + ((size_t)r0 * T + t) * D + c0) = v0;
            *(float2*)(out + ((size_t)(r0 + 8) * T + t) * D + c0) = v1;
        }
    }
}

// ---------------------------------------------------------------------------
// kernel_launch: pure kernel launches (graph-capturable, allocation-free)
// ---------------------------------------------------------------------------
extern "C" void kernel_launch(void* const* d_in, const int* in_sizes, int n_in,
                              void* d_out, int out_size)
{
    const float* X0 = (const float*)d_in[0];   // [BATCH, D]
    const float* A  = (const float*)d_in[1];   // [D, D]
    if (n_in >= 2 && in_sizes[0] == DD && in_sizes[1] == BATCH * D) {
        const float* tmp = X0; X0 = A; A = tmp;  // defensive: metadata order swapped
    }
    float* out = (float*)d_out;

    float* Wb = nullptr;
    cudaGetSymbolAddress((void**)&Wb, g_W);
#define WP(k) (Wb + (size_t)(k) * DD)

    cudaFuncSetAttribute(traj_imma_kernel,
                         cudaFuncAttributeMaxDynamicSharedMemorySize, SMEM_TRAJ);

    // 1) B = A + I ; zero amax accumulators
    initB_kernel<<<DD / 256, 256>>>(A);

    // 2) B powers, serial depth 4: B2; {B3,B4}; {B5..B8}; {B9,B10}
    mm_batch_kernel<<<dim3(8, 8, 1), 256>>>(WP(1), WP(1), WP(2));
    mm_batch_kernel<<<dim3(8, 8, 2), 256>>>(WP(2), WP(1), WP(3));
    mm_batch_kernel<<<dim3(8, 8, 4), 256>>>(WP(4), WP(1), WP(5));
    mm_batch_kernel<<<dim3(8, 8, 2), 256>>>(WP(8), WP(1), WP(9));

    // 3) X quantization (independent of chain)
    amax_x_kernel<<<(BATCH * D) / 1024, 256>>>(X0);
    quant_x_kernel<<<(BATCH * D) / 1024, 256>>>(X0);

    // 4) All 100 M[t] from the series (fp32 + per-t amax), then quantize
    gen_m_kernel<<<128, 256>>>();
    quant_m_kernel<<<(T * DD) / 1024, 256>>>();

    // 5) Main einsum on tensor cores (int8 mma.sync, shared-scale split-2)
    traj_imma_kernel<<<dim3(BATCH / 128, D / 128, T), 256, SMEM_TRAJ>>>(out);

#undef WP
    (void)n_in; (void)out_size;
}

// round 12
// speedup vs baseline: 6.5762x; 6.5762x over previous
#include <cuda_runtime.h>
#include <cuda_bf16.h>

// Problem constants
#define D        256
#define DD       65536
#define BATCH    4096
#define T        100
#define DT_STEP  0.05f
#define NPOW     11          // z_k terms k=1..11; tail (1.6)^12/12! ~ 5e-7

typedef unsigned int u32;
typedef unsigned long long u64t;

// ---------------------------------------------------------------------------
// Device scratch (static globals; no allocation anywhere)
// ---------------------------------------------------------------------------
__device__ float          g_W[12ull * DD];              // B^k, k=1..11 (slot 0 unused)
__device__ __nv_bfloat16  g_Whi[(size_t)NPOW * DD];     // bf16 hi of B^k (slot k-1)
__device__ __nv_bfloat16  g_Wlo[(size_t)NPOW * DD];     // bf16 lo
__device__ __nv_bfloat16  g_Xhi[(size_t)BATCH * D];
__device__ __nv_bfloat16  g_Xlo[(size_t)BATCH * D];
__device__ float          g_Z[(size_t)NPOW * BATCH * D]; // z_k = x*(B^T)^k (slot k-1)

// ---------------------------------------------------------------------------
// PTX helpers (baseline ISA only — compute_103-safe)
// ---------------------------------------------------------------------------
__device__ __forceinline__ u32 smem_u32(const void* p) {
    u32 a;
    asm("{ .reg .u64 t; cvta.to.shared.u64 t, %1; cvt.u32.u64 %0, t; }" : "=r"(a) : "l"(p));
    return a;
}
__device__ __forceinline__ void cpa16(u32 dst, const void* src) {
    asm volatile("cp.async.cg.shared.global [%0], [%1], 16;" :: "r"(dst), "l"(src) : "memory");
}
__device__ __forceinline__ void cpa_commit() { asm volatile("cp.async.commit_group;" ::: "memory"); }
template <int N>
__device__ __forceinline__ void cpa_wait() {
    asm volatile("cp.async.wait_group %0;" :: "n"(N) : "memory");
}
__device__ __forceinline__ void ldm4(u32* r, u32 a) {
    asm volatile("ldmatrix.sync.aligned.m8n8.x4.shared.b16 {%0,%1,%2,%3}, [%4];"
                 : "=r"(r[0]), "=r"(r[1]), "=r"(r[2]), "=r"(r[3]) : "r"(a));
}
__device__ __forceinline__ void mma16816(float* c, const u32* a, u32 b0, u32 b1) {
    asm volatile("mma.sync.aligned.m16n8k16.row.col.f32.bf16.bf16.f32 "
                 "{%0,%1,%2,%3}, {%4,%5,%6,%7}, {%8,%9}, {%0,%1,%2,%3};"
                 : "+f"(c[0]), "+f"(c[1]), "+f"(c[2]), "+f"(c[3])
                 : "r"(a[0]), "r"(a[1]), "r"(a[2]), "r"(a[3]), "r"(b0), "r"(b1));
}
__device__ __forceinline__ u64t pack_dup(float v) {
    u64t r;
    asm("mov.b64 %0, {%1, %1};" : "=l"(r) : "f"(v));
    return r;
}
__device__ __forceinline__ void fma2(u64t& d, u64t a, u64t b) {
    asm("fma.rn.f32x2 %0, %1, %2, %0;" : "+l"(d) : "l"(a), "l"(b));
}
__device__ __forceinline__ u64t mul2(u64t a, u64t b) {
    u64t r;
    asm("mul.rn.f32x2 %0, %1, %2;" : "=l"(r) : "l"(a), "l"(b));
    return r;
}

#define SWZ(o) ((o) ^ (((o) >> 3) & 0x70))

// ---------------------------------------------------------------------------
// initB: g_W[1] = B = A + I
// ---------------------------------------------------------------------------
__global__ void initB_kernel(const float* __restrict__ A) {
    int i = blockIdx.x * blockDim.x + threadIdx.x;   // 0..DD-1
    int r = i >> 8, c = i & 255;
    g_W[DD + i] = A[i] + ((r == c) ? 1.0f : 0.0f);
}

// ---------------------------------------------------------------------------
// Batched small 256x256x256 fp32 matmul: C[z] = X @ Y[z]  (proven R5-R9)
// ---------------------------------------------------------------------------
__global__ void __launch_bounds__(256)
mm_batch_kernel(const float* __restrict__ X,
                const float* __restrict__ Y0,
                float* __restrict__ C0)
{
    const float* __restrict__ Y = Y0 + (size_t)blockIdx.z * DD;
    float* __restrict__ C = C0 + (size_t)blockIdx.z * DD;
    const int rowBase = blockIdx.y * 32;
    const int colBase = blockIdx.x * 32;

    __shared__ float Xs[32][34];
    __shared__ float Ys[32][32];

    const int tid = threadIdx.x;
    const int lrow = tid >> 3;
    const int lq   = (tid & 7) * 4;
    const int tx = tid & 15;
    const int ty = tid >> 4;

    const float* xPtr = X + (size_t)(rowBase + lrow) * D + lq;
    const float* yPtr = Y + (size_t)lrow * D + colBase + lq;

    float4 xv = *(const float4*)xPtr;
    float4 yv = *(const float4*)yPtr;

    float a00 = 0.f, a01 = 0.f, a10 = 0.f, a11 = 0.f;

    for (int d0 = 0; d0 < D; d0 += 32) {
        __syncthreads();
        Xs[lq + 0][lrow] = xv.x; Xs[lq + 1][lrow] = xv.y;
        Xs[lq + 2][lrow] = xv.z; Xs[lq + 3][lrow] = xv.w;
        *(float4*)&Ys[lrow][lq] = yv;
        __syncthreads();

        if (d0 + 32 < D) {
            xv = *(const float4*)(xPtr + d0 + 32);
            yv = *(const float4*)(yPtr + (size_t)(d0 + 32) * D);
        }

#pragma unroll
        for (int kk = 0; kk < 32; ++kk) {
            float2 a = *(const float2*)&Xs[kk][ty * 2];
            float2 b = *(const float2*)&Ys[kk][tx * 2];
            a00 += a.x * b.x; a01 += a.x * b.y;
            a10 += a.y * b.x; a11 += a.y * b.y;
        }
    }

    int gr = rowBase + ty * 2;
    int gc = colBase + tx * 2;
    float2 v0; v0.x = a00; v0.y = a01;
    float2 v1; v1.x = a10; v1.y = a11;
    *(float2*)&C[(size_t)gr * D + gc] = v0;
    *(float2*)&C[(size_t)(gr + 1) * D + gc] = v1;
}

// ---------------------------------------------------------------------------
// split_w: B^k (k=1..NPOW) -> bf16 hi/lo. 4 elems/thread.
// ---------------------------------------------------------------------------
__global__ void split_w_kernel() {
    size_t i = ((size_t)blockIdx.x * 256 + threadIdx.x) * 4;
    float4 v = *(const float4*)(g_W + DD + i);   // W[1] starts at DD
    float xs[4] = {v.x, v.y, v.z, v.w};
#pragma unroll
    for (int j = 0; j < 4; ++j) {
        __nv_bfloat16 h = __float2bfloat16(xs[j]);
        g_Whi[i + j] = h;
        g_Wlo[i + j] = __float2bfloat16(xs[j] - __bfloat162float(h));
    }
}

// ---------------------------------------------------------------------------
// split_x: X0 -> bf16 hi/lo. 4 elems/thread.
// ---------------------------------------------------------------------------
__global__ void split_x_kernel(const float* __restrict__ X0) {
    size_t i = ((size_t)blockIdx.x * 256 + threadIdx.x) * 4;
    float4 v = *(const float4*)(X0 + i);
    float xs[4] = {v.x, v.y, v.z, v.w};
#pragma unroll
    for (int j = 0; j < 4; ++j) {
        __nv_bfloat16 h = __float2bfloat16(xs[j]);
        g_Xhi[i + j] = h;
        g_Xlo[i + j] = __float2bfloat16(xs[j] - __bfloat162float(h));
    }
}

// ---------------------------------------------------------------------------
// zgemm: z_k[b,j] = sum_d x[b,d]*B^k[j,d], bf16 split-3 mma.sync.
// Verbatim transplant of the R7 traj kernel (measured rel_err 4.3e-6);
// blockIdx.z now selects the power k, output is z (no t interleave).
// CTA 128x128xK256, 8 warps, warp tile 64x32, double-buffered cp.async.
// grid (32, 2, NPOW), 256 threads.
// ---------------------------------------------------------------------------
#define TB_XHI 0
#define TB_XLO 16384
#define TB_MHI 32768
#define TB_MLO 49152
#define BUFSZ  65536
#define SMEM_Z (2 * BUFSZ)   // 128 KB dynamic

__global__ void __launch_bounds__(256)
zgemm_kernel()
{
    extern __shared__ char dsm[];
    const u32 sb = smem_u32(dsm);
    const int tid = threadIdx.x;
    const int lane = tid & 31;
    const int wid = tid >> 5;
    const int kz = blockIdx.z;                 // power index (k = kz+1)
    const int bBase = blockIdx.x * 128;
    const int nBase = blockIdx.y * 128;

    const __nv_bfloat16* __restrict__ xh = g_Xhi + (size_t)bBase * D;
    const __nv_bfloat16* __restrict__ xl = g_Xlo + (size_t)bBase * D;
    const __nv_bfloat16* __restrict__ mh = g_Whi + (size_t)kz * DD + (size_t)nBase * D;
    const __nv_bfloat16* __restrict__ ml = g_Wlo + (size_t)kz * DD + (size_t)nBase * D;
    float* __restrict__ zout = g_Z + (size_t)kz * (BATCH * D);

    const int wm = (wid & 1) * 64;
    const int wn = (wid >> 1) * 32;
    const int aRow  = wm + (lane & 15);
    const u32 aColB = (u32)(((lane >> 4) * 8) * 2);
    const int bRow  = wn + ((lane >> 4) << 3) + (lane & 7);
    const u32 bColB = (u32)((((lane >> 3) & 1) * 8) * 2);

    float acc[4][4][4];
#pragma unroll
    for (int mi = 0; mi < 4; ++mi)
#pragma unroll
        for (int nf = 0; nf < 4; ++nf)
#pragma unroll
            for (int r = 0; r < 4; ++r) acc[mi][nf][r] = 0.0f;

    auto load_chunk = [&](int buf, int cd) {
        u32 sbuf = sb + (u32)buf * BUFSZ;
#pragma unroll
        for (int it = 0; it < 4; ++it) {
            int v = tid + it * 256;
            int r = v >> 3, j = v & 7;
            u32 off = SWZ((u32)(r * 128 + j * 16));
            size_t g = (size_t)r * D + cd + j * 8;
            cpa16(sbuf + TB_XHI + off, xh + g);
            cpa16(sbuf + TB_XLO + off, xl + g);
            cpa16(sbuf + TB_MHI + off, mh + g);
            cpa16(sbuf + TB_MLO + off, ml + g);
        }
        cpa_commit();
    };

    load_chunk(0, 0);

    for (int c = 0; c < 4; ++c) {
        if (c < 3) { load_chunk((c + 1) & 1, (c + 1) * 64); cpa_wait<1>(); }
        else       { cpa_wait<0>(); }
        __syncthreads();

        const u32 sbuf = sb + (u32)(c & 1) * BUFSZ;

#pragma unroll
        for (int k16 = 0; k16 < 4; ++k16) {
            const u32 kb = (u32)(k16 * 32);

            u32 bh[8], bl[8];
            {
                u32 o0 = SWZ((u32)(bRow * 128) + kb + bColB);
                u32 o1 = SWZ((u32)((bRow + 16) * 128) + kb + bColB);
                ldm4(bh,     sbuf + TB_MHI + o0);
                ldm4(bh + 4, sbuf + TB_MHI + o1);
                ldm4(bl,     sbuf + TB_MLO + o0);
                ldm4(bl + 4, sbuf + TB_MLO + o1);
            }

            u32 af[4][4];
#pragma unroll
            for (int mi = 0; mi < 4; ++mi) {
                u32 oa = SWZ((u32)((aRow + mi * 16) * 128) + kb + aColB);
                ldm4(af[mi], sbuf + TB_XHI + oa);
            }
#pragma unroll
            for (int mi = 0; mi < 4; ++mi)
#pragma unroll
                for (int nf = 0; nf < 4; ++nf) {
                    mma16816(acc[mi][nf], af[mi], bh[nf * 2], bh[nf * 2 + 1]);
                    mma16816(acc[mi][nf], af[mi], bl[nf * 2], bl[nf * 2 + 1]);
                }
#pragma unroll
            for (int mi = 0; mi < 4; ++mi) {
                u32 oa = SWZ((u32)((aRow + mi * 16) * 128) + kb + aColB);
                ldm4(af[mi], sbuf + TB_XLO + oa);
            }
#pragma unroll
            for (int mi = 0; mi < 4; ++mi)
#pragma unroll
                for (int nf = 0; nf < 4; ++nf)
                    mma16816(acc[mi][nf], af[mi], bh[nf * 2], bh[nf * 2 + 1]);
        }
        __syncthreads();
    }

    // epilogue: z[b, j]
    const int gr = lane >> 2;
    const int gc = (lane & 3) * 2;
#pragma unroll
    for (int mi = 0; mi < 4; ++mi) {
#pragma unroll
        for (int nf = 0; nf < 4; ++nf) {
            int r0 = bBase + wm + mi * 16 + gr;
            int c0 = nBase + wn + nf * 8 + gc;
            float2 v0; v0.x = acc[mi][nf][0]; v0.y = acc[mi][nf][1];
            float2 v1; v1.x = acc[mi][nf][2]; v1.y = acc[mi][nf][3];
            *(float2*)(zout + (size_t)r0 * D + c0) = v0;
            *(float2*)(zout + (size_t)(r0 + 8) * D + c0) = v1;
        }
    }
}

// ---------------------------------------------------------------------------
// combine: out[b,t,c] = e^{-s_t} * ( x[b,c] + sum_{k=1..NPOW} s_t^k/k! * z_k[b,c] ).
// Thread holds x + all z_k for its 8 cols in registers (packed f32x2),
// loops t, writes 2x16B per t. CTA = 32 b x 64 cols. grid (128, 4).
// ---------------------------------------------------------------------------
__global__ void __launch_bounds__(256)
combine_kernel(const float* __restrict__ X0, float* __restrict__ out)
{
    const int tid = threadIdx.x;
    const int cg = tid & 7;
    const int r  = tid >> 3;
    const int b  = blockIdx.x * 32 + r;
    const int c  = blockIdx.y * 64 + cg * 8;

    u64t zz[NPOW + 1][4];
    {
        const float* p = X0 + (size_t)b * D + c;
        ulonglong2 u0 = *(const ulonglong2*)(p);
        ulonglong2 u1 = *(const ulonglong2*)(p + 4);
        zz[0][0] = u0.x; zz[0][1] = u0.y; zz[0][2] = u1.x; zz[0][3] = u1.y;
    }
#pragma unroll
    for (int k = 1; k <= NPOW; ++k) {
        const float* p = g_Z + (size_t)(k - 1) * (BATCH * D) + (size_t)b * D + c;
        ulonglong2 u0 = *(const ulonglong2*)(p);
        ulonglong2 u1 = *(const ulonglong2*)(p + 4);
        zz[k][0] = u0.x; zz[k][1] = u0.y; zz[k][2] = u1.x; zz[k][3] = u1.y;
    }

    float* obase = out + (size_t)b * T * D + c;
    for (int t = 0; t < T; ++t) {
        float s = DT_STEP * (float)t;
        float ck = expf(-s);
        u64t w = pack_dup(ck);
        u64t a0 = mul2(w, zz[0][0]);
        u64t a1 = mul2(w, zz[0][1]);
        u64t a2 = mul2(w, zz[0][2]);
        u64t a3 = mul2(w, zz[0][3]);
#pragma unroll
        for (int k = 1; k <= NPOW; ++k) {
            ck *= s / (float)k;
            w = pack_dup(ck);
            fma2(a0, w, zz[k][0]);
            fma2(a1, w, zz[k][1]);
            fma2(a2, w, zz[k][2]);
            fma2(a3, w, zz[k][3]);
        }
        ulonglong2 v0; v0.x = a0; v0.y = a1;
        ulonglong2 v1; v1.x = a2; v1.y = a3;
        float* o = obase + (size_t)t * D;
        *(ulonglong2*)(o) = v0;
        *(ulonglong2*)(o + 4) = v1;
    }
}

// ---------------------------------------------------------------------------
// kernel_launch: pure kernel launches (graph-capturable, allocation-free)
// ---------------------------------------------------------------------------
extern "C" void kernel_launch(void* const* d_in, const int* in_sizes, int n_in,
                              void* d_out, int out_size)
{
    const float* X0 = (const float*)d_in[0];   // [BATCH, D]
    const float* A  = (const float*)d_in[1];   // [D, D]
    if (n_in >= 2 && in_sizes[0] == DD && in_sizes[1] == BATCH * D) {
        const float* tmp = X0; X0 = A; A = tmp;  // defensive: metadata order swapped
    }
    float* out = (float*)d_out;

    float* Wb = nullptr;
    cudaGetSymbolAddress((void**)&Wb, g_W);
#define WP(k) (Wb + (size_t)(k) * DD)

    cudaFuncSetAttribute(zgemm_kernel,
                         cudaFuncAttributeMaxDynamicSharedMemorySize, SMEM_Z);

    // 1) B = A + I
    initB_kernel<<<DD / 256, 256>>>(A);

    // 2) B powers, serial depth 4: B2; {B3,B4}; {B5..B8}; {B9..B11}
    mm_batch_kernel<<<dim3(8, 8, 1), 256>>>(WP(1), WP(1), WP(2));
    mm_batch_kernel<<<dim3(8, 8, 2), 256>>>(WP(2), WP(1), WP(3));
    mm_batch_kernel<<<dim3(8, 8, 4), 256>>>(WP(4), WP(1), WP(5));
    mm_batch_kernel<<<dim3(8, 8, 3), 256>>>(WP(8), WP(1), WP(9));

    // 3) bf16 splits (W chain result + X)
    split_w_kernel<<<(NPOW * DD) / 1024, 256>>>();
    split_x_kernel<<<(BATCH * D) / 1024, 256>>>(X0);

    // 4) z_k = x * (B^T)^k for k=1..NPOW — 11 independent GEMMs, one launch
    zgemm_kernel<<<dim3(BATCH / 128, D / 128, NPOW), 256, SMEM_Z>>>();

    // 5) Combine: weighted z-sum per (b, t), streamed to out
    combine_kernel<<<dim3(BATCH / 32, D / 64), 256>>>(X0, out);

#undef WP
    (void)n_in; (void)out_size;
}